// round 1
// baseline (speedup 1.0000x reference)
#include <cuda_runtime.h>
#include <cuda_bf16.h>
#include <math.h>

// Problem constants
#define BATCH 2
#define SEQ   2048
#define DMODEL 1024
#define NHEADS 16
#define DK    64
#define MROWS (BATCH*SEQ)          // 4096

// Scratch (allocation-free rule: __device__ globals)
__device__ float g_Q[BATCH*NHEADS*SEQ*DK];   // [B,H,S,dk]
__device__ float g_K[BATCH*NHEADS*SEQ*DK];
__device__ float g_V[BATCH*NHEADS*SEQ*DK];
__device__ float g_CTX[MROWS*DMODEL];        // [B,S,D]

// ---------------------------------------------------------------------------
// GEMM: out = A(4096x1024) @ W(1024x1024)^T   (both row-major, inner dim = k)
// 64x64 tile, TK=16, 16x16 threads, 4x4 microtile.
// mode 0: write to split-head dst (Q/K/V).  mode 1: plain row-major dst.
// ---------------------------------------------------------------------------
__global__ void __launch_bounds__(256) qkv_gemm_kernel(
    const float* __restrict__ x,
    const float* __restrict__ wq,
    const float* __restrict__ wk,
    const float* __restrict__ wv)
{
    const float* W   = (blockIdx.z == 0) ? wq : (blockIdx.z == 1) ? wk : wv;
    float*       dst = (blockIdx.z == 0) ? g_Q : (blockIdx.z == 1) ? g_K : g_V;

    const int m0 = blockIdx.y * 64;
    const int n0 = blockIdx.x * 64;
    const int tx = threadIdx.x, ty = threadIdx.y;
    const int tid = ty * 16 + tx;

    __shared__ float As[64][17];
    __shared__ float Bs[64][17];

    float acc[4][4] = {};

    for (int k0 = 0; k0 < DMODEL; k0 += 16) {
        #pragma unroll
        for (int i = 0; i < 4; i++) {
            int idx = tid + i * 256;
            int r = idx >> 4, c = idx & 15;
            As[r][c] = x[(size_t)(m0 + r) * DMODEL + k0 + c];
            Bs[r][c] = W[(size_t)(n0 + r) * DMODEL + k0 + c];
        }
        __syncthreads();
        #pragma unroll
        for (int kk = 0; kk < 16; kk++) {
            float a[4], b[4];
            #pragma unroll
            for (int i = 0; i < 4; i++) a[i] = As[ty * 4 + i][kk];
            #pragma unroll
            for (int j = 0; j < 4; j++) b[j] = Bs[tx * 4 + j][kk];
            #pragma unroll
            for (int i = 0; i < 4; i++)
                #pragma unroll
                for (int j = 0; j < 4; j++)
                    acc[i][j] = fmaf(a[i], b[j], acc[i][j]);
        }
        __syncthreads();
    }

    // split-head write: m -> (b,s), n -> (h,d);  dst[((b*H+h)*S+s)*DK+d]
    #pragma unroll
    for (int i = 0; i < 4; i++) {
        int m = m0 + ty * 4 + i;
        int b = m >> 11, s = m & 2047;
        #pragma unroll
        for (int j = 0; j < 4; j++) {
            int n = n0 + tx * 4 + j;
            int h = n >> 6, d = n & 63;
            dst[(((size_t)(b * NHEADS + h)) * SEQ + s) * DK + d] = acc[i][j];
        }
    }
}

__global__ void __launch_bounds__(256) out_gemm_kernel(
    const float* __restrict__ wo,
    float* __restrict__ out)
{
    const int m0 = blockIdx.y * 64;
    const int n0 = blockIdx.x * 64;
    const int tx = threadIdx.x, ty = threadIdx.y;
    const int tid = ty * 16 + tx;

    __shared__ float As[64][17];
    __shared__ float Bs[64][17];

    float acc[4][4] = {};

    for (int k0 = 0; k0 < DMODEL; k0 += 16) {
        #pragma unroll
        for (int i = 0; i < 4; i++) {
            int idx = tid + i * 256;
            int r = idx >> 4, c = idx & 15;
            As[r][c] = g_CTX[(size_t)(m0 + r) * DMODEL + k0 + c];
            Bs[r][c] = wo[(size_t)(n0 + r) * DMODEL + k0 + c];
        }
        __syncthreads();
        #pragma unroll
        for (int kk = 0; kk < 16; kk++) {
            float a[4], b[4];
            #pragma unroll
            for (int i = 0; i < 4; i++) a[i] = As[ty * 4 + i][kk];
            #pragma unroll
            for (int j = 0; j < 4; j++) b[j] = Bs[tx * 4 + j][kk];
            #pragma unroll
            for (int i = 0; i < 4; i++)
                #pragma unroll
                for (int j = 0; j < 4; j++)
                    acc[i][j] = fmaf(a[i], b[j], acc[i][j]);
        }
        __syncthreads();
    }

    #pragma unroll
    for (int i = 0; i < 4; i++)
        #pragma unroll
        for (int j = 0; j < 4; j++)
            out[(size_t)(m0 + ty * 4 + i) * DMODEL + n0 + tx * 4 + j] = acc[i][j];
}

// ---------------------------------------------------------------------------
// Flash attention (fp32): one CTA per (q-tile of 64 rows, b*h).
// K/V streamed in 32-row tiles, online softmax, bias added from GMEM.
// T5-style: NO 1/sqrt(dk) scaling.
// ---------------------------------------------------------------------------
#define QT 64
#define KT 32

__global__ void __launch_bounds__(256) attn_kernel(
    const float* __restrict__ bias)
{
    const int qt = blockIdx.x;        // 0..31
    const int bh = blockIdx.y;        // 0..31
    const int b  = bh >> 4;
    const int h  = bh & 15;

    const float* Qg   = g_Q + ((size_t)bh * SEQ + qt * QT) * DK;
    const float* Kb   = g_K + (size_t)bh * SEQ * DK;
    const float* Vb   = g_V + (size_t)bh * SEQ * DK;
    const float* bb   = bias + ((size_t)h * SEQ + qt * QT) * SEQ;

    __shared__ float Qs[QT][DK + 1];   // 64x65
    __shared__ float Ks[KT][DK + 1];   // 32x65
    __shared__ float Vs[KT][DK + 1];   // 32x65
    __shared__ float Ss[QT][KT + 1];   // 64x33
    __shared__ float rm[QT], rl[QT], rs[QT];

    const int tx = threadIdx.x, ty = threadIdx.y;
    const int tid = ty * 16 + tx;

    // load Q tile (4096 elems)
    #pragma unroll
    for (int it = 0; it < 16; it++) {
        int idx = tid + it * 256;
        Qs[idx >> 6][idx & 63] = Qg[idx];
    }
    if (tid < QT) { rm[tid] = -INFINITY; rl[tid] = 0.f; }

    float o[4][4] = {};
    __syncthreads();

    for (int kt = 0; kt < SEQ / KT; kt++) {
        const float* Kg = Kb + (size_t)kt * KT * DK;
        const float* Vg = Vb + (size_t)kt * KT * DK;
        #pragma unroll
        for (int it = 0; it < 8; it++) {
            int idx = tid + it * 256;
            int r = idx >> 6, c = idx & 63;
            Ks[r][c] = Kg[idx];
            Vs[r][c] = Vg[idx];
        }
        __syncthreads();

        // S = Q K^T + bias   (thread tile: 4 rows x 2 cols of 64x32)
        float sa[4][2];
        #pragma unroll
        for (int i = 0; i < 4; i++)
            #pragma unroll
            for (int j = 0; j < 2; j++)
                sa[i][j] = bb[(size_t)(ty * 4 + i) * SEQ + kt * KT + tx * 2 + j];
        #pragma unroll 8
        for (int k = 0; k < DK; k++) {
            float a[4], c2[2];
            #pragma unroll
            for (int i = 0; i < 4; i++) a[i] = Qs[ty * 4 + i][k];
            #pragma unroll
            for (int j = 0; j < 2; j++) c2[j] = Ks[tx * 2 + j][k];
            #pragma unroll
            for (int i = 0; i < 4; i++)
                #pragma unroll
                for (int j = 0; j < 2; j++)
                    sa[i][j] = fmaf(a[i], c2[j], sa[i][j]);
        }
        #pragma unroll
        for (int i = 0; i < 4; i++)
            #pragma unroll
            for (int j = 0; j < 2; j++)
                Ss[ty * 4 + i][tx * 2 + j] = sa[i][j];
        __syncthreads();

        // per-row online softmax update (one thread per row)
        if (tid < QT) {
            float mt = -INFINITY;
            #pragma unroll 8
            for (int c = 0; c < KT; c++) mt = fmaxf(mt, Ss[tid][c]);
            float mnew = fmaxf(rm[tid], mt);
            float sc = __expf(rm[tid] - mnew);
            float sum = 0.f;
            #pragma unroll 8
            for (int c = 0; c < KT; c++) {
                float e = __expf(Ss[tid][c] - mnew);
                Ss[tid][c] = e;
                sum += e;
            }
            rl[tid] = rl[tid] * sc + sum;
            rm[tid] = mnew;
            rs[tid] = sc;
        }
        __syncthreads();

        // O = O*scale + P @ V   (thread tile 4x4 of 64x64)
        #pragma unroll
        for (int i = 0; i < 4; i++) {
            float scl = rs[ty * 4 + i];
            #pragma unroll
            for (int j = 0; j < 4; j++) o[i][j] *= scl;
        }
        #pragma unroll 8
        for (int k = 0; k < KT; k++) {
            float p[4], v[4];
            #pragma unroll
            for (int i = 0; i < 4; i++) p[i] = Ss[ty * 4 + i][k];
            #pragma unroll
            for (int j = 0; j < 4; j++) v[j] = Vs[k][tx * 4 + j];
            #pragma unroll
            for (int i = 0; i < 4; i++)
                #pragma unroll
                for (int j = 0; j < 4; j++)
                    o[i][j] = fmaf(p[i], v[j], o[i][j]);
        }
        __syncthreads();
    }

    // normalize and write to CTX in [B,S,D] layout (merge heads)
    #pragma unroll
    for (int i = 0; i < 4; i++) {
        int r = ty * 4 + i;
        float inv = 1.f / rl[r];
        int s = qt * QT + r;
        #pragma unroll
        for (int j = 0; j < 4; j++) {
            int d = tx * 4 + j;
            g_CTX[((size_t)b * SEQ + s) * DMODEL + h * DK + d] = o[i][j] * inv;
        }
    }
}

// ---------------------------------------------------------------------------
extern "C" void kernel_launch(void* const* d_in, const int* in_sizes, int n_in,
                              void* d_out, int out_size)
{
    const float* x    = (const float*)d_in[0];
    const float* bias = (const float*)d_in[1];
    const float* wq   = (const float*)d_in[2];
    const float* wk   = (const float*)d_in[3];
    const float* wv   = (const float*)d_in[4];
    const float* wo   = (const float*)d_in[5];
    float* out = (float*)d_out;

    dim3 blk(16, 16);
    // 1) QKV projections (fused over grid.z)
    qkv_gemm_kernel<<<dim3(DMODEL / 64, MROWS / 64, 3), blk>>>(x, wq, wk, wv);
    // 2) flash attention
    attn_kernel<<<dim3(SEQ / QT, BATCH * NHEADS), dim3(16, 16)>>>(bias);
    // 3) output projection
    out_gemm_kernel<<<dim3(DMODEL / 64, MROWS / 64), blk>>>(wo, out);
}

// round 2
// speedup vs baseline: 2.0362x; 2.0362x over previous
#include <cuda_runtime.h>
#include <cuda_bf16.h>
#include <math.h>

#define BATCH 2
#define SEQ   2048
#define DMODEL 1024
#define NHEADS 16
#define DK    64
#define MROWS (BATCH*SEQ)   // 4096

// Scratch
__device__ float g_Q [BATCH*NHEADS*SEQ*DK];   // [bh][s][d]
__device__ float g_K [BATCH*NHEADS*SEQ*DK];   // [bh][s][d]
__device__ float g_Vt[BATCH*NHEADS*DK*SEQ];   // [bh][d][s]  (transposed V)
__device__ float g_CTX[MROWS*DMODEL];         // [b*S+s][D]

// ---------------------------------------------------------------------------
// helpers
// ---------------------------------------------------------------------------
__device__ __forceinline__ void split2(float x, float y, unsigned &hi, unsigned &lo) {
    __nv_bfloat16 xh = __float2bfloat16_rn(x);
    __nv_bfloat16 yh = __float2bfloat16_rn(y);
    __nv_bfloat16 xl = __float2bfloat16_rn(x - __bfloat162float(xh));
    __nv_bfloat16 yl = __float2bfloat16_rn(y - __bfloat162float(yh));
    __nv_bfloat162 hv(xh, yh), lv(xl, yl);
    hi = *reinterpret_cast<unsigned*>(&hv);
    lo = *reinterpret_cast<unsigned*>(&lv);
}

__device__ __forceinline__ void mma_bf16(float (&d)[4],
    unsigned a0, unsigned a1, unsigned a2, unsigned a3,
    unsigned b0, unsigned b1)
{
    asm volatile(
        "mma.sync.aligned.m16n8k16.row.col.f32.bf16.bf16.f32 "
        "{%0,%1,%2,%3},{%4,%5,%6,%7},{%8,%9},{%0,%1,%2,%3};\n"
        : "+f"(d[0]), "+f"(d[1]), "+f"(d[2]), "+f"(d[3])
        : "r"(a0), "r"(a1), "r"(a2), "r"(a3), "r"(b0), "r"(b1));
}

// ---------------------------------------------------------------------------
// Projection GEMM: C[4096,1024] = A @ W^T, bf16 hi/lo 3-way split on tensor cores
// CTA tile 128x128, BK=32, 256 threads (8 warps: 4 along m, 2 along n),
// warp tile 32x64 (2 m16 x 8 n8).
// z selects W and destination: 0->Q, 1->K, 2->V(transposed store)
// ---------------------------------------------------------------------------
__global__ void __launch_bounds__(256, 1) qkv_mma_kernel(
    const float* __restrict__ x,
    const float* __restrict__ wq,
    const float* __restrict__ wk,
    const float* __restrict__ wv)
{
    const int z = blockIdx.z;
    const float* __restrict__ W = (z == 0) ? wq : (z == 1) ? wk : wv;

    const int m0 = blockIdx.y * 128;
    const int n0 = blockIdx.x * 128;
    const int tid  = threadIdx.x;
    const int warp = tid >> 5;
    const int lane = tid & 31;
    const int gid  = lane >> 2;
    const int qid  = lane & 3;
    const int wm = (warp & 3) * 32;
    const int wn = (warp >> 2) * 64;

    __shared__ unsigned As_h[128][17], As_l[128][17];
    __shared__ unsigned Bs_h[128][17], Bs_l[128][17];

    float c[2][8][4];
    #pragma unroll
    for (int i = 0; i < 2; i++)
        #pragma unroll
        for (int t = 0; t < 8; t++)
            #pragma unroll
            for (int j = 0; j < 4; j++) c[i][t][j] = 0.f;

    for (int k0 = 0; k0 < DMODEL; k0 += 32) {
        #pragma unroll
        for (int i = 0; i < 4; i++) {
            int i4 = tid + i * 256;      // 0..1023 float4 slots
            int r  = i4 >> 3;            // 0..127
            int c4 = i4 & 7;             // 0..7
            unsigned h0, l0, h1, l1;
            float4 av = *(const float4*)(x + (size_t)(m0 + r) * DMODEL + k0 + c4 * 4);
            split2(av.x, av.y, h0, l0); split2(av.z, av.w, h1, l1);
            As_h[r][c4*2] = h0; As_h[r][c4*2+1] = h1;
            As_l[r][c4*2] = l0; As_l[r][c4*2+1] = l1;
            float4 bv = *(const float4*)(W + (size_t)(n0 + r) * DMODEL + k0 + c4 * 4);
            split2(bv.x, bv.y, h0, l0); split2(bv.z, bv.w, h1, l1);
            Bs_h[r][c4*2] = h0; Bs_h[r][c4*2+1] = h1;
            Bs_l[r][c4*2] = l0; Bs_l[r][c4*2+1] = l1;
        }
        __syncthreads();

        #pragma unroll
        for (int ck = 0; ck < 2; ck++) {
            unsigned ah[2][4], al[2][4];
            #pragma unroll
            for (int mi = 0; mi < 2; mi++) {
                int r = wm + mi * 16;
                ah[mi][0] = As_h[r+gid  ][ck*8+qid];
                ah[mi][1] = As_h[r+gid+8][ck*8+qid];
                ah[mi][2] = As_h[r+gid  ][ck*8+qid+4];
                ah[mi][3] = As_h[r+gid+8][ck*8+qid+4];
                al[mi][0] = As_l[r+gid  ][ck*8+qid];
                al[mi][1] = As_l[r+gid+8][ck*8+qid];
                al[mi][2] = As_l[r+gid  ][ck*8+qid+4];
                al[mi][3] = As_l[r+gid+8][ck*8+qid+4];
            }
            #pragma unroll
            for (int tn = 0; tn < 8; tn++) {
                int nr = wn + tn * 8 + gid;
                unsigned bh0 = Bs_h[nr][ck*8+qid], bh1 = Bs_h[nr][ck*8+qid+4];
                unsigned bl0 = Bs_l[nr][ck*8+qid], bl1 = Bs_l[nr][ck*8+qid+4];
                #pragma unroll
                for (int mi = 0; mi < 2; mi++) {
                    mma_bf16(c[mi][tn], ah[mi][0], ah[mi][1], ah[mi][2], ah[mi][3], bh0, bh1);
                    mma_bf16(c[mi][tn], ah[mi][0], ah[mi][1], ah[mi][2], ah[mi][3], bl0, bl1);
                    mma_bf16(c[mi][tn], al[mi][0], al[mi][1], al[mi][2], al[mi][3], bh0, bh1);
                }
            }
        }
        __syncthreads();
    }

    // epilogue
    float* dstQ = (z == 0) ? g_Q : g_K;   // for z<2
    #pragma unroll
    for (int mi = 0; mi < 2; mi++) {
        #pragma unroll
        for (int tn = 0; tn < 8; tn++) {
            int n = n0 + wn + tn * 8 + qid * 2;
            int h = n >> 6, d = n & 63;
            #pragma unroll
            for (int half = 0; half < 2; half++) {
                int r = m0 + wm + mi * 16 + gid + half * 8;
                int b = r >> 11, s = r & 2047;
                float v0 = c[mi][tn][half*2], v1 = c[mi][tn][half*2+1];
                if (z < 2) {
                    float2 p = make_float2(v0, v1);
                    *(float2*)(dstQ + (((size_t)(b*NHEADS + h)) * SEQ + s) * DK + d) = p;
                } else {
                    size_t base = ((size_t)(b*NHEADS + h) * DK + d) * SEQ + s;
                    g_Vt[base] = v0;
                    g_Vt[base + SEQ] = v1;
                }
            }
        }
    }
}

// Output projection: out = CTX @ Wo^T (same structure, plain epilogue)
__global__ void __launch_bounds__(256, 1) out_mma_kernel(
    const float* __restrict__ wo,
    float* __restrict__ out)
{
    const int m0 = blockIdx.y * 128;
    const int n0 = blockIdx.x * 128;
    const int tid  = threadIdx.x;
    const int warp = tid >> 5;
    const int lane = tid & 31;
    const int gid  = lane >> 2;
    const int qid  = lane & 3;
    const int wm = (warp & 3) * 32;
    const int wn = (warp >> 2) * 64;

    __shared__ unsigned As_h[128][17], As_l[128][17];
    __shared__ unsigned Bs_h[128][17], Bs_l[128][17];

    float c[2][8][4];
    #pragma unroll
    for (int i = 0; i < 2; i++)
        #pragma unroll
        for (int t = 0; t < 8; t++)
            #pragma unroll
            for (int j = 0; j < 4; j++) c[i][t][j] = 0.f;

    for (int k0 = 0; k0 < DMODEL; k0 += 32) {
        #pragma unroll
        for (int i = 0; i < 4; i++) {
            int i4 = tid + i * 256;
            int r  = i4 >> 3;
            int c4 = i4 & 7;
            unsigned h0, l0, h1, l1;
            float4 av = *(const float4*)(g_CTX + (size_t)(m0 + r) * DMODEL + k0 + c4 * 4);
            split2(av.x, av.y, h0, l0); split2(av.z, av.w, h1, l1);
            As_h[r][c4*2] = h0; As_h[r][c4*2+1] = h1;
            As_l[r][c4*2] = l0; As_l[r][c4*2+1] = l1;
            float4 bv = *(const float4*)(wo + (size_t)(n0 + r) * DMODEL + k0 + c4 * 4);
            split2(bv.x, bv.y, h0, l0); split2(bv.z, bv.w, h1, l1);
            Bs_h[r][c4*2] = h0; Bs_h[r][c4*2+1] = h1;
            Bs_l[r][c4*2] = l0; Bs_l[r][c4*2+1] = l1;
        }
        __syncthreads();

        #pragma unroll
        for (int ck = 0; ck < 2; ck++) {
            unsigned ah[2][4], al[2][4];
            #pragma unroll
            for (int mi = 0; mi < 2; mi++) {
                int r = wm + mi * 16;
                ah[mi][0] = As_h[r+gid  ][ck*8+qid];
                ah[mi][1] = As_h[r+gid+8][ck*8+qid];
                ah[mi][2] = As_h[r+gid  ][ck*8+qid+4];
                ah[mi][3] = As_h[r+gid+8][ck*8+qid+4];
                al[mi][0] = As_l[r+gid  ][ck*8+qid];
                al[mi][1] = As_l[r+gid+8][ck*8+qid];
                al[mi][2] = As_l[r+gid  ][ck*8+qid+4];
                al[mi][3] = As_l[r+gid+8][ck*8+qid+4];
            }
            #pragma unroll
            for (int tn = 0; tn < 8; tn++) {
                int nr = wn + tn * 8 + gid;
                unsigned bh0 = Bs_h[nr][ck*8+qid], bh1 = Bs_h[nr][ck*8+qid+4];
                unsigned bl0 = Bs_l[nr][ck*8+qid], bl1 = Bs_l[nr][ck*8+qid+4];
                #pragma unroll
                for (int mi = 0; mi < 2; mi++) {
                    mma_bf16(c[mi][tn], ah[mi][0], ah[mi][1], ah[mi][2], ah[mi][3], bh0, bh1);
                    mma_bf16(c[mi][tn], ah[mi][0], ah[mi][1], ah[mi][2], ah[mi][3], bl0, bl1);
                    mma_bf16(c[mi][tn], al[mi][0], al[mi][1], al[mi][2], al[mi][3], bh0, bh1);
                }
            }
        }
        __syncthreads();
    }

    #pragma unroll
    for (int mi = 0; mi < 2; mi++) {
        #pragma unroll
        for (int tn = 0; tn < 8; tn++) {
            int n = n0 + wn + tn * 8 + qid * 2;
            #pragma unroll
            for (int half = 0; half < 2; half++) {
                int r = m0 + wm + mi * 16 + gid + half * 8;
                float2 p = make_float2(c[mi][tn][half*2], c[mi][tn][half*2+1]);
                *(float2*)(out + (size_t)r * DMODEL + n) = p;
            }
        }
    }
}

// ---------------------------------------------------------------------------
// Flash attention on tensor cores (bf16 hi/lo split, fp32 accumulate).
// CTA: 128 threads (4 warps), 64 q-rows per CTA (16 per warp), K/V chunks of 64.
// ---------------------------------------------------------------------------
__global__ void __launch_bounds__(128, 3) attn_mma_kernel(
    const float* __restrict__ bias)
{
    const int q0 = blockIdx.x * 64;
    const int bh = blockIdx.y;
    const int b  = bh >> 4;
    const int h  = bh & 15;

    const int tid  = threadIdx.x;
    const int warp = tid >> 5;
    const int lane = tid & 31;
    const int gid  = lane >> 2;
    const int qid  = lane & 3;

    const float* __restrict__ Qg  = g_Q  + ((size_t)bh * SEQ + q0 + warp * 16) * DK;
    const float* __restrict__ Kg  = g_K  + (size_t)bh * SEQ * DK;
    const float* __restrict__ Vtg = g_Vt + (size_t)bh * DK * SEQ;
    const float* __restrict__ bb  = bias + ((size_t)h * SEQ + q0 + warp * 16) * SEQ;

    __shared__ unsigned Kh[64][33], Kl[64][33];   // [key][d-pair]
    __shared__ unsigned Vh[64][33], Vl[64][33];   // [d][key-pair]

    // Q fragments (persistent): 4 k16 chunks
    unsigned qh[4][4], ql[4][4];
    #pragma unroll
    for (int ck = 0; ck < 4; ck++) {
        float2 v;
        v = *(const float2*)(Qg + (size_t)gid * DK + ck*16 + qid*2);
        split2(v.x, v.y, qh[ck][0], ql[ck][0]);
        v = *(const float2*)(Qg + (size_t)(gid+8) * DK + ck*16 + qid*2);
        split2(v.x, v.y, qh[ck][1], ql[ck][1]);
        v = *(const float2*)(Qg + (size_t)gid * DK + ck*16 + qid*2 + 8);
        split2(v.x, v.y, qh[ck][2], ql[ck][2]);
        v = *(const float2*)(Qg + (size_t)(gid+8) * DK + ck*16 + qid*2 + 8);
        split2(v.x, v.y, qh[ck][3], ql[ck][3]);
    }

    float m1 = -INFINITY, m2 = -INFINITY, l1 = 0.f, l2 = 0.f;
    float o[8][4];
    #pragma unroll
    for (int t = 0; t < 8; t++)
        #pragma unroll
        for (int j = 0; j < 4; j++) o[t][j] = 0.f;

    for (int kt = 0; kt < SEQ / 64; kt++) {
        // load K chunk [64 keys][64 d] and Vt chunk [64 d][64 keys]
        #pragma unroll
        for (int i = 0; i < 8; i++) {
            int i4 = tid + i * 128;
            int r  = i4 >> 4;          // 0..63
            int c4 = i4 & 15;          // 0..15
            unsigned h0, l0, h1, l1r;
            float4 kv = *(const float4*)(Kg + (size_t)(kt*64 + r) * DK + c4 * 4);
            split2(kv.x, kv.y, h0, l0); split2(kv.z, kv.w, h1, l1r);
            Kh[r][c4*2] = h0; Kh[r][c4*2+1] = h1;
            Kl[r][c4*2] = l0; Kl[r][c4*2+1] = l1r;
            float4 vv = *(const float4*)(Vtg + (size_t)r * SEQ + kt*64 + c4 * 4);
            split2(vv.x, vv.y, h0, l0); split2(vv.z, vv.w, h1, l1r);
            Vh[r][c4*2] = h0; Vh[r][c4*2+1] = h1;
            Vl[r][c4*2] = l0; Vl[r][c4*2+1] = l1r;
        }
        __syncthreads();

        // S fragments initialized with bias
        float s[8][4];
        #pragma unroll
        for (int tn = 0; tn < 8; tn++) {
            float2 b01 = *(const float2*)(bb + (size_t)gid * SEQ + kt*64 + tn*8 + qid*2);
            float2 b23 = *(const float2*)(bb + (size_t)(gid+8) * SEQ + kt*64 + tn*8 + qid*2);
            s[tn][0] = b01.x; s[tn][1] = b01.y; s[tn][2] = b23.x; s[tn][3] = b23.y;
        }

        // S += Q @ K^T (3-way split)
        #pragma unroll
        for (int tn = 0; tn < 8; tn++) {
            int key = tn * 8 + gid;
            #pragma unroll
            for (int ck = 0; ck < 4; ck++) {
                unsigned bh0 = Kh[key][ck*8+qid], bh1 = Kh[key][ck*8+qid+4];
                unsigned bl0 = Kl[key][ck*8+qid], bl1 = Kl[key][ck*8+qid+4];
                mma_bf16(s[tn], qh[ck][0], qh[ck][1], qh[ck][2], qh[ck][3], bh0, bh1);
                mma_bf16(s[tn], qh[ck][0], qh[ck][1], qh[ck][2], qh[ck][3], bl0, bl1);
                mma_bf16(s[tn], ql[ck][0], ql[ck][1], ql[ck][2], ql[ck][3], bh0, bh1);
            }
        }

        // online softmax (rows gid and gid+8, reduce across 4-thread groups)
        float rmax1 = -INFINITY, rmax2 = -INFINITY;
        #pragma unroll
        for (int tn = 0; tn < 8; tn++) {
            rmax1 = fmaxf(rmax1, fmaxf(s[tn][0], s[tn][1]));
            rmax2 = fmaxf(rmax2, fmaxf(s[tn][2], s[tn][3]));
        }
        rmax1 = fmaxf(rmax1, __shfl_xor_sync(0xffffffffu, rmax1, 1));
        rmax1 = fmaxf(rmax1, __shfl_xor_sync(0xffffffffu, rmax1, 2));
        rmax2 = fmaxf(rmax2, __shfl_xor_sync(0xffffffffu, rmax2, 1));
        rmax2 = fmaxf(rmax2, __shfl_xor_sync(0xffffffffu, rmax2, 2));

        float mn1 = fmaxf(m1, rmax1), mn2 = fmaxf(m2, rmax2);
        float sc1 = __expf(m1 - mn1), sc2 = __expf(m2 - mn2);
        m1 = mn1; m2 = mn2;

        float sum1 = 0.f, sum2 = 0.f;
        #pragma unroll
        for (int tn = 0; tn < 8; tn++) {
            s[tn][0] = __expf(s[tn][0] - mn1); sum1 += s[tn][0];
            s[tn][1] = __expf(s[tn][1] - mn1); sum1 += s[tn][1];
            s[tn][2] = __expf(s[tn][2] - mn2); sum2 += s[tn][2];
            s[tn][3] = __expf(s[tn][3] - mn2); sum2 += s[tn][3];
        }
        sum1 += __shfl_xor_sync(0xffffffffu, sum1, 1);
        sum1 += __shfl_xor_sync(0xffffffffu, sum1, 2);
        sum2 += __shfl_xor_sync(0xffffffffu, sum2, 1);
        sum2 += __shfl_xor_sync(0xffffffffu, sum2, 2);
        l1 = l1 * sc1 + sum1;
        l2 = l2 * sc2 + sum2;

        #pragma unroll
        for (int tn = 0; tn < 8; tn++) {
            o[tn][0] *= sc1; o[tn][1] *= sc1; o[tn][2] *= sc2; o[tn][3] *= sc2;
        }

        // P fragments (C-frag -> A-frag in registers)
        unsigned ph[4][4], pl[4][4];
        #pragma unroll
        for (int ck = 0; ck < 4; ck++) {
            split2(s[2*ck  ][0], s[2*ck  ][1], ph[ck][0], pl[ck][0]);
            split2(s[2*ck  ][2], s[2*ck  ][3], ph[ck][1], pl[ck][1]);
            split2(s[2*ck+1][0], s[2*ck+1][1], ph[ck][2], pl[ck][2]);
            split2(s[2*ck+1][2], s[2*ck+1][3], ph[ck][3], pl[ck][3]);
        }

        // O += P @ V (3-way split)
        #pragma unroll
        for (int tn = 0; tn < 8; tn++) {
            int dcol = tn * 8 + gid;
            #pragma unroll
            for (int ck = 0; ck < 4; ck++) {
                unsigned bh0 = Vh[dcol][ck*8+qid], bh1 = Vh[dcol][ck*8+qid+4];
                unsigned bl0 = Vl[dcol][ck*8+qid], bl1 = Vl[dcol][ck*8+qid+4];
                mma_bf16(o[tn], ph[ck][0], ph[ck][1], ph[ck][2], ph[ck][3], bh0, bh1);
                mma_bf16(o[tn], ph[ck][0], ph[ck][1], ph[ck][2], ph[ck][3], bl0, bl1);
                mma_bf16(o[tn], pl[ck][0], pl[ck][1], pl[ck][2], pl[ck][3], bh0, bh1);
            }
        }
        __syncthreads();
    }

    // epilogue: normalize, merge heads into CTX [b*S+s][D]
    float inv1 = 1.f / l1, inv2 = 1.f / l2;
    int s1 = q0 + warp * 16 + gid;
    int s2 = s1 + 8;
    #pragma unroll
    for (int tn = 0; tn < 8; tn++) {
        int d = h * DK + tn * 8 + qid * 2;
        float2 p1 = make_float2(o[tn][0] * inv1, o[tn][1] * inv1);
        float2 p2 = make_float2(o[tn][2] * inv2, o[tn][3] * inv2);
        *(float2*)(g_CTX + ((size_t)b * SEQ + s1) * DMODEL + d) = p1;
        *(float2*)(g_CTX + ((size_t)b * SEQ + s2) * DMODEL + d) = p2;
    }
}

// ---------------------------------------------------------------------------
extern "C" void kernel_launch(void* const* d_in, const int* in_sizes, int n_in,
                              void* d_out, int out_size)
{
    const float* x    = (const float*)d_in[0];
    const float* bias = (const float*)d_in[1];
    const float* wq   = (const float*)d_in[2];
    const float* wk   = (const float*)d_in[3];
    const float* wv   = (const float*)d_in[4];
    const float* wo   = (const float*)d_in[5];
    float* out = (float*)d_out;

    qkv_mma_kernel<<<dim3(DMODEL/128, MROWS/128, 3), 256>>>(x, wq, wk, wv);
    attn_mma_kernel<<<dim3(SEQ/64, BATCH*NHEADS), 128>>>(bias);
    out_mma_kernel<<<dim3(DMODEL/128, MROWS/128), 256>>>(wo, out);
}

// round 3
// speedup vs baseline: 3.2071x; 1.5750x over previous
#include <cuda_runtime.h>
#include <cuda_bf16.h>
#include <math.h>

#define BATCH 2
#define SEQ   2048
#define DMODEL 1024
#define NHEADS 16
#define DK    64
#define MROWS (BATCH*SEQ)   // 4096

// ---------------------------------------------------------------------------
// Scratch (__device__ globals; packed bf16 hi/lo, pairs along k in one u32)
// Unified A-space rows: 0..4095 = x ; 4096+1024*z = W_z (q,k,v,o); 8192.. = CTX
// ---------------------------------------------------------------------------
__device__ unsigned g_ah[12288 * 512];
__device__ unsigned g_al[12288 * 512];
__device__ unsigned g_qh[32 * 2048 * 32];  // [bh][s][dpair]
__device__ unsigned g_ql[32 * 2048 * 32];
__device__ unsigned g_kh[32 * 2048 * 32];
__device__ unsigned g_kl[32 * 2048 * 32];
__device__ __nv_bfloat16 g_vth[32 * 64 * 2048];  // [bh][d][s]
__device__ __nv_bfloat16 g_vtl[32 * 64 * 2048];

// ---------------------------------------------------------------------------
// helpers
// ---------------------------------------------------------------------------
__device__ __forceinline__ void split2(float x, float y, unsigned &hi, unsigned &lo) {
    __nv_bfloat16 xh = __float2bfloat16_rn(x);
    __nv_bfloat16 yh = __float2bfloat16_rn(y);
    __nv_bfloat16 xl = __float2bfloat16_rn(x - __bfloat162float(xh));
    __nv_bfloat16 yl = __float2bfloat16_rn(y - __bfloat162float(yh));
    __nv_bfloat162 hv(xh, yh), lv(xl, yl);
    hi = *reinterpret_cast<unsigned*>(&hv);
    lo = *reinterpret_cast<unsigned*>(&lv);
}

__device__ __forceinline__ void mma_bf16(float (&d)[4],
    unsigned a0, unsigned a1, unsigned a2, unsigned a3,
    unsigned b0, unsigned b1)
{
    asm volatile(
        "mma.sync.aligned.m16n8k16.row.col.f32.bf16.bf16.f32 "
        "{%0,%1,%2,%3},{%4,%5,%6,%7},{%8,%9},{%0,%1,%2,%3};\n"
        : "+f"(d[0]), "+f"(d[1]), "+f"(d[2]), "+f"(d[3])
        : "r"(a0), "r"(a1), "r"(a2), "r"(a3), "r"(b0), "r"(b1));
}

__device__ __forceinline__ void cp_async16(unsigned dst, const void* src) {
    asm volatile("cp.async.cg.shared.global [%0], [%1], 16;\n" :: "r"(dst), "l"(src));
}
__device__ __forceinline__ void cp_commit() {
    asm volatile("cp.async.commit_group;\n" ::: "memory");
}
__device__ __forceinline__ void cp_wait0() {
    asm volatile("cp.async.wait_group 0;\n" ::: "memory");
}

// ---------------------------------------------------------------------------
// 1) split prepass: x + 4 weights -> g_ah/g_al (packed bf16 hi/lo pairs)
// ---------------------------------------------------------------------------
__global__ void __launch_bounds__(256) split_kernel(
    const float* __restrict__ x,  const float* __restrict__ wq,
    const float* __restrict__ wk, const float* __restrict__ wv,
    const float* __restrict__ wo)
{
    size_t i = (size_t)blockIdx.x * 256 + threadIdx.x;   // pair index
    size_t row = i >> 9;
    int col = (int)(i & 511);
    const float* src;
    if      (row < 4096) src = x  + row * 1024;
    else if (row < 5120) src = wq + (row - 4096) * 1024;
    else if (row < 6144) src = wk + (row - 5120) * 1024;
    else if (row < 7168) src = wv + (row - 6144) * 1024;
    else                 src = wo + (row - 7168) * 1024;
    float2 v = *(const float2*)(src + col * 2);
    unsigned hi, lo;
    split2(v.x, v.y, hi, lo);
    g_ah[i] = hi;
    g_al[i] = lo;
}

// ---------------------------------------------------------------------------
// 2) GEMM: C[128x128 tiles] = A @ B^T, bf16 hi/lo 3-term, cp.async 2-stage.
//    smem: [buf2][arr4: Ah,Al,Bh,Bl][128][20] u32 = 80KB dynamic
//    mode: 0->Q, 1->K, 2->Vt(bf16 split), 3->out(fp32)
// ---------------------------------------------------------------------------
#define SMG(buf,arr,r,c) dynsm[ (((buf)*4 + (arr))*2560) + (r)*20 + (c) ]

__global__ void __launch_bounds__(256, 2) gemm_kernel(int mode_base, float* __restrict__ outp)
{
    extern __shared__ unsigned dynsm[];
    const int mode = mode_base + blockIdx.z;
    const int aRow0 = (mode == 3) ? 8192 : 0;
    const int bRow0 = 4096 + mode * 1024;

    const int m0 = blockIdx.y * 128;
    const int n0 = blockIdx.x * 128;
    const int tid  = threadIdx.x;
    const int warp = tid >> 5;
    const int lane = tid & 31;
    const int gid  = lane >> 2;
    const int qid  = lane & 3;
    const int wm = (warp & 3) * 32;
    const int wn = (warp >> 2) * 64;

    const unsigned* aH = g_ah + (size_t)(aRow0 + m0) * 512;
    const unsigned* aL = g_al + (size_t)(aRow0 + m0) * 512;
    const unsigned* bH = g_ah + (size_t)(bRow0 + n0) * 512;
    const unsigned* bL = g_al + (size_t)(bRow0 + n0) * 512;
    const unsigned smbase = (unsigned)__cvta_generic_to_shared(dynsm);

    float c[2][8][4];
    #pragma unroll
    for (int i = 0; i < 2; i++)
        #pragma unroll
        for (int t = 0; t < 8; t++)
            #pragma unroll
            for (int j = 0; j < 4; j++) c[i][t][j] = 0.f;

    // issue helper (inlined twice)
    #define GEMM_ISSUE(BUFSEL, KP0) do {                                          \
        const unsigned* _g[4] = {aH, aL, bH, bL};                                 \
        _Pragma("unroll")                                                         \
        for (int arr = 0; arr < 4; arr++) {                                       \
            _Pragma("unroll")                                                     \
            for (int j = 0; j < 2; j++) {                                         \
                int idx = tid + j * 256;                                          \
                int r = idx >> 2, c4 = (idx & 3) * 4;                             \
                cp_async16(smbase + ((((BUFSEL)*4 + arr)*2560 + r*20 + c4) << 2), \
                           _g[arr] + (size_t)r * 512 + (KP0) + c4);               \
            }                                                                     \
        }                                                                         \
    } while (0)

    GEMM_ISSUE(0, 0);
    cp_commit();

    int buf = 0;
    for (int k0 = 0; k0 < 32; k0++) {
        cp_wait0();
        __syncthreads();
        if (k0 + 1 < 32) { GEMM_ISSUE(buf ^ 1, (k0 + 1) * 16); cp_commit(); }

        #pragma unroll
        for (int ck = 0; ck < 2; ck++) {
            unsigned ah[2][4], al[2][4];
            #pragma unroll
            for (int mi = 0; mi < 2; mi++) {
                int r = wm + mi * 16;
                ah[mi][0] = SMG(buf, 0, r + gid,     ck*8 + qid);
                ah[mi][1] = SMG(buf, 0, r + gid + 8, ck*8 + qid);
                ah[mi][2] = SMG(buf, 0, r + gid,     ck*8 + qid + 4);
                ah[mi][3] = SMG(buf, 0, r + gid + 8, ck*8 + qid + 4);
                al[mi][0] = SMG(buf, 1, r + gid,     ck*8 + qid);
                al[mi][1] = SMG(buf, 1, r + gid + 8, ck*8 + qid);
                al[mi][2] = SMG(buf, 1, r + gid,     ck*8 + qid + 4);
                al[mi][3] = SMG(buf, 1, r + gid + 8, ck*8 + qid + 4);
            }
            #pragma unroll
            for (int tn = 0; tn < 8; tn++) {
                int nr = wn + tn * 8 + gid;
                unsigned bh0 = SMG(buf, 2, nr, ck*8 + qid);
                unsigned bh1 = SMG(buf, 2, nr, ck*8 + qid + 4);
                unsigned bl0 = SMG(buf, 3, nr, ck*8 + qid);
                unsigned bl1 = SMG(buf, 3, nr, ck*8 + qid + 4);
                #pragma unroll
                for (int mi = 0; mi < 2; mi++) {
                    mma_bf16(c[mi][tn], ah[mi][0], ah[mi][1], ah[mi][2], ah[mi][3], bh0, bh1);
                    mma_bf16(c[mi][tn], ah[mi][0], ah[mi][1], ah[mi][2], ah[mi][3], bl0, bl1);
                    mma_bf16(c[mi][tn], al[mi][0], al[mi][1], al[mi][2], al[mi][3], bh0, bh1);
                }
            }
        }
        buf ^= 1;
    }

    // epilogue
    #pragma unroll
    for (int mi = 0; mi < 2; mi++) {
        #pragma unroll
        for (int tn = 0; tn < 8; tn++) {
            int n = n0 + wn + tn * 8 + qid * 2;
            int h = n >> 6, d = n & 63;
            #pragma unroll
            for (int half = 0; half < 2; half++) {
                int r = m0 + wm + mi * 16 + gid + half * 8;
                float v0 = c[mi][tn][half * 2], v1 = c[mi][tn][half * 2 + 1];
                if (mode == 3) {
                    *(float2*)(outp + (size_t)r * DMODEL + n) = make_float2(v0, v1);
                } else {
                    int b = r >> 11, s = r & 2047;
                    int bh = b * NHEADS + h;
                    if (mode < 2) {
                        unsigned hi, lo;
                        split2(v0, v1, hi, lo);
                        size_t idx = ((size_t)bh * 2048 + s) * 32 + (d >> 1);
                        if (mode == 0) { g_qh[idx] = hi; g_ql[idx] = lo; }
                        else           { g_kh[idx] = hi; g_kl[idx] = lo; }
                    } else {
                        __nv_bfloat16 h0 = __float2bfloat16_rn(v0);
                        __nv_bfloat16 l0 = __float2bfloat16_rn(v0 - __bfloat162float(h0));
                        __nv_bfloat16 h1 = __float2bfloat16_rn(v1);
                        __nv_bfloat16 l1 = __float2bfloat16_rn(v1 - __bfloat162float(h1));
                        size_t base = ((size_t)bh * 64 + d) * 2048 + s;
                        g_vth[base] = h0;          g_vtl[base] = l0;
                        g_vth[base + 2048] = h1;   g_vtl[base + 2048] = l1;
                    }
                }
            }
        }
    }
}

// ---------------------------------------------------------------------------
// 3) Flash attention: bf16 hi/lo inputs (precomputed), cp.async 2-stage.
//    grid (2, 512): x=batch, y=h*32+qt. CTA 128 thr, 64 q-rows, KV chunk 64.
//    smem: [buf2][arr4: Kh,Kl,Vh,Vl][64][36] u32 = 72KB dynamic
// ---------------------------------------------------------------------------
#define SMA(buf,arr,r,c) dynsm[ (((buf)*4 + (arr))*2304) + (r)*36 + (c) ]

__global__ void __launch_bounds__(128, 3) attn_kernel(const float* __restrict__ bias)
{
    extern __shared__ unsigned dynsm[];
    const int b  = blockIdx.x;
    const int h  = blockIdx.y >> 5;
    const int qt = blockIdx.y & 31;
    const int bh = b * NHEADS + h;
    const int q0 = qt * 64;

    const int tid  = threadIdx.x;
    const int warp = tid >> 5;
    const int lane = tid & 31;
    const int gid  = lane >> 2;
    const int qid  = lane & 3;

    const unsigned* kHb = g_kh + (size_t)bh * 2048 * 32;
    const unsigned* kLb = g_kl + (size_t)bh * 2048 * 32;
    const unsigned* vHb = (const unsigned*)(g_vth + (size_t)bh * 64 * 2048);
    const unsigned* vLb = (const unsigned*)(g_vtl + (size_t)bh * 64 * 2048);
    const float* bb = bias + ((size_t)h * SEQ + q0 + warp * 16) * SEQ;
    const unsigned smbase = (unsigned)__cvta_generic_to_shared(dynsm);

    // persistent Q fragments
    unsigned qh[4][4], ql[4][4];
    {
        const unsigned* qhp = g_qh + ((size_t)bh * 2048 + q0 + warp * 16) * 32;
        const unsigned* qlp = g_ql + ((size_t)bh * 2048 + q0 + warp * 16) * 32;
        #pragma unroll
        for (int ck = 0; ck < 4; ck++) {
            qh[ck][0] = qhp[(size_t)gid * 32       + ck*8 + qid];
            qh[ck][1] = qhp[(size_t)(gid + 8) * 32 + ck*8 + qid];
            qh[ck][2] = qhp[(size_t)gid * 32       + ck*8 + qid + 4];
            qh[ck][3] = qhp[(size_t)(gid + 8) * 32 + ck*8 + qid + 4];
            ql[ck][0] = qlp[(size_t)gid * 32       + ck*8 + qid];
            ql[ck][1] = qlp[(size_t)(gid + 8) * 32 + ck*8 + qid];
            ql[ck][2] = qlp[(size_t)gid * 32       + ck*8 + qid + 4];
            ql[ck][3] = qlp[(size_t)(gid + 8) * 32 + ck*8 + qid + 4];
        }
    }

    #define ATTN_ISSUE(BUFSEL, KT) do {                                              \
        _Pragma("unroll")                                                            \
        for (int j = 0; j < 4; j++) {                                                \
            int idx = tid + j * 128;                                                 \
            int r = idx >> 3, c4 = (idx & 7) * 4;                                    \
            cp_async16(smbase + ((((BUFSEL)*4 + 0)*2304 + r*36 + c4) << 2),          \
                       kHb + (size_t)((KT)*64 + r) * 32 + c4);                       \
            cp_async16(smbase + ((((BUFSEL)*4 + 1)*2304 + r*36 + c4) << 2),          \
                       kLb + (size_t)((KT)*64 + r) * 32 + c4);                       \
            cp_async16(smbase + ((((BUFSEL)*4 + 2)*2304 + r*36 + c4) << 2),          \
                       vHb + (size_t)r * 1024 + (KT)*32 + c4);                       \
            cp_async16(smbase + ((((BUFSEL)*4 + 3)*2304 + r*36 + c4) << 2),          \
                       vLb + (size_t)r * 1024 + (KT)*32 + c4);                       \
        }                                                                            \
    } while (0)

    float m1 = -INFINITY, m2 = -INFINITY, l1 = 0.f, l2 = 0.f;
    float o[8][4];
    #pragma unroll
    for (int t = 0; t < 8; t++)
        #pragma unroll
        for (int j = 0; j < 4; j++) o[t][j] = 0.f;

    ATTN_ISSUE(0, 0);
    cp_commit();

    int buf = 0;
    for (int kt = 0; kt < SEQ / 64; kt++) {
        cp_wait0();
        __syncthreads();
        if (kt + 1 < SEQ / 64) { ATTN_ISSUE(buf ^ 1, kt + 1); cp_commit(); }

        // S = bias + Q K^T
        float s[8][4];
        #pragma unroll
        for (int tn = 0; tn < 8; tn++) {
            float2 b01 = *(const float2*)(bb + (size_t)gid * SEQ       + kt*64 + tn*8 + qid*2);
            float2 b23 = *(const float2*)(bb + (size_t)(gid + 8) * SEQ + kt*64 + tn*8 + qid*2);
            s[tn][0] = b01.x; s[tn][1] = b01.y; s[tn][2] = b23.x; s[tn][3] = b23.y;
        }
        #pragma unroll
        for (int tn = 0; tn < 8; tn++) {
            int key = tn * 8 + gid;
            #pragma unroll
            for (int ck = 0; ck < 4; ck++) {
                unsigned bh0 = SMA(buf, 0, key, ck*8 + qid);
                unsigned bh1 = SMA(buf, 0, key, ck*8 + qid + 4);
                unsigned bl0 = SMA(buf, 1, key, ck*8 + qid);
                unsigned bl1 = SMA(buf, 1, key, ck*8 + qid + 4);
                mma_bf16(s[tn], qh[ck][0], qh[ck][1], qh[ck][2], qh[ck][3], bh0, bh1);
                mma_bf16(s[tn], qh[ck][0], qh[ck][1], qh[ck][2], qh[ck][3], bl0, bl1);
                mma_bf16(s[tn], ql[ck][0], ql[ck][1], ql[ck][2], ql[ck][3], bh0, bh1);
            }
        }

        // online softmax (rows gid, gid+8; reduce over quad)
        float rmax1 = -INFINITY, rmax2 = -INFINITY;
        #pragma unroll
        for (int tn = 0; tn < 8; tn++) {
            rmax1 = fmaxf(rmax1, fmaxf(s[tn][0], s[tn][1]));
            rmax2 = fmaxf(rmax2, fmaxf(s[tn][2], s[tn][3]));
        }
        rmax1 = fmaxf(rmax1, __shfl_xor_sync(0xffffffffu, rmax1, 1));
        rmax1 = fmaxf(rmax1, __shfl_xor_sync(0xffffffffu, rmax1, 2));
        rmax2 = fmaxf(rmax2, __shfl_xor_sync(0xffffffffu, rmax2, 1));
        rmax2 = fmaxf(rmax2, __shfl_xor_sync(0xffffffffu, rmax2, 2));

        float mn1 = fmaxf(m1, rmax1), mn2 = fmaxf(m2, rmax2);
        float sc1 = __expf(m1 - mn1), sc2 = __expf(m2 - mn2);
        m1 = mn1; m2 = mn2;

        float sum1 = 0.f, sum2 = 0.f;
        #pragma unroll
        for (int tn = 0; tn < 8; tn++) {
            s[tn][0] = __expf(s[tn][0] - mn1); sum1 += s[tn][0];
            s[tn][1] = __expf(s[tn][1] - mn1); sum1 += s[tn][1];
            s[tn][2] = __expf(s[tn][2] - mn2); sum2 += s[tn][2];
            s[tn][3] = __expf(s[tn][3] - mn2); sum2 += s[tn][3];
        }
        sum1 += __shfl_xor_sync(0xffffffffu, sum1, 1);
        sum1 += __shfl_xor_sync(0xffffffffu, sum1, 2);
        sum2 += __shfl_xor_sync(0xffffffffu, sum2, 1);
        sum2 += __shfl_xor_sync(0xffffffffu, sum2, 2);
        l1 = l1 * sc1 + sum1;
        l2 = l2 * sc2 + sum2;

        #pragma unroll
        for (int tn = 0; tn < 8; tn++) {
            o[tn][0] *= sc1; o[tn][1] *= sc1; o[tn][2] *= sc2; o[tn][3] *= sc2;
        }

        // O += P @ V (split P per k16 chunk to limit reg pressure)
        #pragma unroll
        for (int ck = 0; ck < 4; ck++) {
            unsigned ph[4], pl[4];
            split2(s[2*ck  ][0], s[2*ck  ][1], ph[0], pl[0]);
            split2(s[2*ck  ][2], s[2*ck  ][3], ph[1], pl[1]);
            split2(s[2*ck+1][0], s[2*ck+1][1], ph[2], pl[2]);
            split2(s[2*ck+1][2], s[2*ck+1][3], ph[3], pl[3]);
            #pragma unroll
            for (int tn = 0; tn < 8; tn++) {
                int dcol = tn * 8 + gid;
                unsigned vh0 = SMA(buf, 2, dcol, ck*8 + qid);
                unsigned vh1 = SMA(buf, 2, dcol, ck*8 + qid + 4);
                unsigned vl0 = SMA(buf, 3, dcol, ck*8 + qid);
                unsigned vl1 = SMA(buf, 3, dcol, ck*8 + qid + 4);
                mma_bf16(o[tn], ph[0], ph[1], ph[2], ph[3], vh0, vh1);
                mma_bf16(o[tn], ph[0], ph[1], ph[2], ph[3], vl0, vl1);
                mma_bf16(o[tn], pl[0], pl[1], pl[2], pl[3], vh0, vh1);
            }
        }
        buf ^= 1;
    }

    // epilogue: normalize, split, write CTX rows (8192 + b*2048 + s) of g_ah/g_al
    float inv1 = 1.f / l1, inv2 = 1.f / l2;
    int s1 = q0 + warp * 16 + gid;
    int s2 = s1 + 8;
    size_t row1 = (size_t)(8192 + b * 2048 + s1) * 512;
    size_t row2 = (size_t)(8192 + b * 2048 + s2) * 512;
    #pragma unroll
    for (int tn = 0; tn < 8; tn++) {
        int pair = h * 32 + tn * 4 + qid;
        unsigned hi, lo;
        split2(o[tn][0] * inv1, o[tn][1] * inv1, hi, lo);
        g_ah[row1 + pair] = hi; g_al[row1 + pair] = lo;
        split2(o[tn][2] * inv2, o[tn][3] * inv2, hi, lo);
        g_ah[row2 + pair] = hi; g_al[row2 + pair] = lo;
    }
}

// ---------------------------------------------------------------------------
extern "C" void kernel_launch(void* const* d_in, const int* in_sizes, int n_in,
                              void* d_out, int out_size)
{
    const float* x    = (const float*)d_in[0];
    const float* bias = (const float*)d_in[1];
    const float* wq   = (const float*)d_in[2];
    const float* wk   = (const float*)d_in[3];
    const float* wv   = (const float*)d_in[4];
    const float* wo   = (const float*)d_in[5];
    float* out = (float*)d_out;

    cudaFuncSetAttribute(gemm_kernel, cudaFuncAttributeMaxDynamicSharedMemorySize, 81920);
    cudaFuncSetAttribute(attn_kernel, cudaFuncAttributeMaxDynamicSharedMemorySize, 73728);

    split_kernel<<<16384, 256>>>(x, wq, wk, wv, wo);
    gemm_kernel<<<dim3(8, 32, 3), 256, 81920>>>(0, nullptr);
    attn_kernel<<<dim3(2, 512), 128, 73728>>>(bias);
    gemm_kernel<<<dim3(8, 32, 1), 256, 81920>>>(3, out);
}

// round 5
// speedup vs baseline: 3.6428x; 1.1358x over previous
#include <cuda_runtime.h>
#include <cuda_bf16.h>
#include <math.h>

#define BATCH 2
#define SEQ   2048
#define DMODEL 1024
#define NHEADS 16
#define DK    64
#define MROWS (BATCH*SEQ)   // 4096

// ---------------------------------------------------------------------------
// Scratch (__device__ globals; packed bf16 hi/lo, pairs along k in one u32)
// Unified A-space rows: 0..4095 = x ; 4096+1024*z = W_z (q,k,v,o); 8192.. = CTX
// ---------------------------------------------------------------------------
__device__ unsigned g_ah[12288 * 512];
__device__ unsigned g_al[12288 * 512];
__device__ unsigned g_qh[32 * 2048 * 32];  // [bh][s][dpair]
__device__ unsigned g_ql[32 * 2048 * 32];
__device__ unsigned g_kh[32 * 2048 * 32];
__device__ unsigned g_kl[32 * 2048 * 32];
__device__ __nv_bfloat16 g_vth[32 * 64 * 2048];  // [bh][d][s]
__device__ __nv_bfloat16 g_vtl[32 * 64 * 2048];

// ---------------------------------------------------------------------------
// helpers
// ---------------------------------------------------------------------------
__device__ __forceinline__ void split2(float x, float y, unsigned &hi, unsigned &lo) {
    __nv_bfloat16 xh = __float2bfloat16_rn(x);
    __nv_bfloat16 yh = __float2bfloat16_rn(y);
    __nv_bfloat16 xl = __float2bfloat16_rn(x - __bfloat162float(xh));
    __nv_bfloat16 yl = __float2bfloat16_rn(y - __bfloat162float(yh));
    __nv_bfloat162 hv(xh, yh), lv(xl, yl);
    hi = *reinterpret_cast<unsigned*>(&hv);
    lo = *reinterpret_cast<unsigned*>(&lv);
}

__device__ __forceinline__ void mma_bf16(float (&d)[4],
    unsigned a0, unsigned a1, unsigned a2, unsigned a3,
    unsigned b0, unsigned b1)
{
    asm volatile(
        "mma.sync.aligned.m16n8k16.row.col.f32.bf16.bf16.f32 "
        "{%0,%1,%2,%3},{%4,%5,%6,%7},{%8,%9},{%0,%1,%2,%3};\n"
        : "+f"(d[0]), "+f"(d[1]), "+f"(d[2]), "+f"(d[3])
        : "r"(a0), "r"(a1), "r"(a2), "r"(a3), "r"(b0), "r"(b1));
}

__device__ __forceinline__ void ldsm_x4(unsigned &r0, unsigned &r1,
                                        unsigned &r2, unsigned &r3, unsigned addr)
{
    asm volatile("ldmatrix.sync.aligned.m8n8.x4.shared.b16 {%0,%1,%2,%3}, [%4];\n"
        : "=r"(r0), "=r"(r1), "=r"(r2), "=r"(r3) : "r"(addr));
}

__device__ __forceinline__ void cp_async16(unsigned dst, const void* src) {
    asm volatile("cp.async.cg.shared.global [%0], [%1], 16;\n" :: "r"(dst), "l"(src));
}
__device__ __forceinline__ void cp_commit() {
    asm volatile("cp.async.commit_group;\n" ::: "memory");
}
__device__ __forceinline__ void cp_wait0() {
    asm volatile("cp.async.wait_group 0;\n" ::: "memory");
}

// ---------------------------------------------------------------------------
// 1) split prepass
// ---------------------------------------------------------------------------
__global__ void __launch_bounds__(256) split_kernel(
    const float* __restrict__ x,  const float* __restrict__ wq,
    const float* __restrict__ wk, const float* __restrict__ wv,
    const float* __restrict__ wo)
{
    size_t i = (size_t)blockIdx.x * 256 + threadIdx.x;   // pair index
    size_t row = i >> 9;
    int col = (int)(i & 511);
    const float* src;
    if      (row < 4096) src = x  + row * 1024;
    else if (row < 5120) src = wq + (row - 4096) * 1024;
    else if (row < 6144) src = wk + (row - 5120) * 1024;
    else if (row < 7168) src = wv + (row - 6144) * 1024;
    else                 src = wo + (row - 7168) * 1024;
    float2 v = *(const float2*)(src + col * 2);
    unsigned hi, lo;
    split2(v.x, v.y, hi, lo);
    g_ah[i] = hi;
    g_al[i] = lo;
}

// ---------------------------------------------------------------------------
// 2) GEMM: 128x128 tiles, bf16 hi/lo 3-term, cp.async 2-stage, ldmatrix frags.
//    smem: [buf2][arr4: Ah,Al,Bh,Bl][128][20] u32 = 80KB dynamic
//    mode: 0->Q, 1->K, 2->Vt(bf16 hi+lo), 3->out(fp32)
// ---------------------------------------------------------------------------
__global__ void __launch_bounds__(256, 2) gemm_kernel(int mode_base, float* __restrict__ outp)
{
    extern __shared__ unsigned dynsm[];
    const int mode = mode_base + blockIdx.z;
    const int aRow0 = (mode == 3) ? 8192 : 0;
    const int bRow0 = 4096 + mode * 1024;

    const int m0 = blockIdx.y * 128;
    const int n0 = blockIdx.x * 128;
    const int tid  = threadIdx.x;
    const int warp = tid >> 5;
    const int lane = tid & 31;
    const int gid  = lane >> 2;
    const int qid  = lane & 3;
    const int wm = (warp & 3) * 32;
    const int wn = (warp >> 2) * 64;

    const unsigned* aH = g_ah + (size_t)(aRow0 + m0) * 512;
    const unsigned* aL = g_al + (size_t)(aRow0 + m0) * 512;
    const unsigned* bH = g_ah + (size_t)(bRow0 + n0) * 512;
    const unsigned* bL = g_al + (size_t)(bRow0 + n0) * 512;
    const unsigned smbase = (unsigned)__cvta_generic_to_shared(dynsm);

    // ldmatrix lane-address components
    const int a_r = (lane & 15);            // + wm + mi*16
    const int a_c = (lane >> 4) << 2;       // + ck*8
    const int b_r = ((lane >> 4) & 1) * 8 + (lane & 7);   // + wn + tnp*16
    const int b_c = ((lane >> 3) & 1) << 2;                // + ck*8

    float c[2][8][4];
    #pragma unroll
    for (int i = 0; i < 2; i++)
        #pragma unroll
        for (int t = 0; t < 8; t++)
            #pragma unroll
            for (int j = 0; j < 4; j++) c[i][t][j] = 0.f;

    #define GEMM_ISSUE(BUFSEL, KP0) do {                                          \
        const unsigned* _g[4] = {aH, aL, bH, bL};                                 \
        _Pragma("unroll")                                                         \
        for (int arr = 0; arr < 4; arr++) {                                       \
            _Pragma("unroll")                                                     \
            for (int j = 0; j < 2; j++) {                                         \
                int idx = tid + j * 256;                                          \
                int r = idx >> 2, c4 = (idx & 3) * 4;                             \
                cp_async16(smbase + ((((BUFSEL)*4 + arr)*2560 + r*20 + c4) << 2), \
                           _g[arr] + (size_t)r * 512 + (KP0) + c4);               \
            }                                                                     \
        }                                                                         \
    } while (0)

    GEMM_ISSUE(0, 0);
    cp_commit();

    int buf = 0;
    for (int k0 = 0; k0 < 32; k0++) {
        cp_wait0();
        __syncthreads();
        if (k0 + 1 < 32) { GEMM_ISSUE(buf ^ 1, (k0 + 1) * 16); cp_commit(); }

        #pragma unroll
        for (int ck = 0; ck < 2; ck++) {
            unsigned ah[2][4], al[2][4];
            #pragma unroll
            for (int mi = 0; mi < 2; mi++) {
                unsigned rowoff = (wm + mi * 16 + a_r) * 20 + ck * 8 + a_c;
                ldsm_x4(ah[mi][0], ah[mi][1], ah[mi][2], ah[mi][3],
                        smbase + (((buf*4 + 0)*2560 + rowoff) << 2));
                ldsm_x4(al[mi][0], al[mi][1], al[mi][2], al[mi][3],
                        smbase + (((buf*4 + 1)*2560 + rowoff) << 2));
            }
            #pragma unroll
            for (int tnp = 0; tnp < 4; tnp++) {
                unsigned bh[4], bl[4];
                unsigned rowoff = (wn + tnp * 16 + b_r) * 20 + ck * 8 + b_c;
                ldsm_x4(bh[0], bh[1], bh[2], bh[3],
                        smbase + (((buf*4 + 2)*2560 + rowoff) << 2));
                ldsm_x4(bl[0], bl[1], bl[2], bl[3],
                        smbase + (((buf*4 + 3)*2560 + rowoff) << 2));
                #pragma unroll
                for (int e = 0; e < 2; e++) {
                    int tn = tnp * 2 + e;
                    #pragma unroll
                    for (int mi = 0; mi < 2; mi++) {
                        mma_bf16(c[mi][tn], ah[mi][0], ah[mi][1], ah[mi][2], ah[mi][3], bh[e*2], bh[e*2+1]);
                        mma_bf16(c[mi][tn], ah[mi][0], ah[mi][1], ah[mi][2], ah[mi][3], bl[e*2], bl[e*2+1]);
                        mma_bf16(c[mi][tn], al[mi][0], al[mi][1], al[mi][2], al[mi][3], bh[e*2], bh[e*2+1]);
                    }
                }
            }
        }
        buf ^= 1;
    }

    // epilogue
    #pragma unroll
    for (int mi = 0; mi < 2; mi++) {
        #pragma unroll
        for (int tn = 0; tn < 8; tn++) {
            int n = n0 + wn + tn * 8 + qid * 2;
            int h = n >> 6, d = n & 63;
            #pragma unroll
            for (int half = 0; half < 2; half++) {
                int r = m0 + wm + mi * 16 + gid + half * 8;
                float v0 = c[mi][tn][half * 2], v1 = c[mi][tn][half * 2 + 1];
                if (mode == 3) {
                    *(float2*)(outp + (size_t)r * DMODEL + n) = make_float2(v0, v1);
                } else {
                    int b = r >> 11, s = r & 2047;
                    int bh = b * NHEADS + h;
                    if (mode < 2) {
                        unsigned hi, lo;
                        split2(v0, v1, hi, lo);
                        size_t idx = ((size_t)bh * 2048 + s) * 32 + (d >> 1);
                        if (mode == 0) { g_qh[idx] = hi; g_ql[idx] = lo; }
                        else           { g_kh[idx] = hi; g_kl[idx] = lo; }
                    } else {
                        __nv_bfloat16 h0 = __float2bfloat16_rn(v0);
                        __nv_bfloat16 l0 = __float2bfloat16_rn(v0 - __bfloat162float(h0));
                        __nv_bfloat16 h1 = __float2bfloat16_rn(v1);
                        __nv_bfloat16 l1 = __float2bfloat16_rn(v1 - __bfloat162float(h1));
                        size_t base = ((size_t)bh * 64 + d) * 2048 + s;
                        g_vth[base] = h0;          g_vtl[base] = l0;
                        g_vth[base + 2048] = h1;   g_vtl[base + 2048] = l1;
                    }
                }
            }
        }
    }
}

// ---------------------------------------------------------------------------
// 3) Flash attention: QK 3-term, PV 3-term, cp.async 2-stage, ldmatrix frags.
//    smem: [buf2][arr4: Kh,Kl,Vh,Vl][64][36] u32 = 72KB dynamic
// ---------------------------------------------------------------------------
#define SMAOFF(buf,arr) (((buf)*4 + (arr))*2304)

__global__ void __launch_bounds__(128, 3) attn_kernel(const float* __restrict__ bias)
{
    extern __shared__ unsigned dynsm[];
    const int b  = blockIdx.x;
    const int h  = blockIdx.y >> 5;
    const int qt = blockIdx.y & 31;
    const int bh = b * NHEADS + h;
    const int q0 = qt * 64;

    const int tid  = threadIdx.x;
    const int warp = tid >> 5;
    const int lane = tid & 31;
    const int gid  = lane >> 2;
    const int qid  = lane & 3;

    const unsigned* kHb = g_kh + (size_t)bh * 2048 * 32;
    const unsigned* kLb = g_kl + (size_t)bh * 2048 * 32;
    const unsigned* vHb = (const unsigned*)(g_vth + (size_t)bh * 64 * 2048);
    const unsigned* vLb = (const unsigned*)(g_vtl + (size_t)bh * 64 * 2048);
    const float* bb = bias + ((size_t)h * SEQ + q0 + warp * 16) * SEQ;
    const unsigned smbase = (unsigned)__cvta_generic_to_shared(dynsm);

    const int b_r = ((lane >> 4) & 1) * 8 + (lane & 7);   // + tnp*16
    const int b_c = ((lane >> 3) & 1) << 2;               // + ck*8

    // persistent Q fragments
    unsigned qh[4][4], ql[4][4];
    {
        const unsigned* qhp = g_qh + ((size_t)bh * 2048 + q0 + warp * 16) * 32;
        const unsigned* qlp = g_ql + ((size_t)bh * 2048 + q0 + warp * 16) * 32;
        #pragma unroll
        for (int ck = 0; ck < 4; ck++) {
            qh[ck][0] = qhp[(size_t)gid * 32       + ck*8 + qid];
            qh[ck][1] = qhp[(size_t)(gid + 8) * 32 + ck*8 + qid];
            qh[ck][2] = qhp[(size_t)gid * 32       + ck*8 + qid + 4];
            qh[ck][3] = qhp[(size_t)(gid + 8) * 32 + ck*8 + qid + 4];
            ql[ck][0] = qlp[(size_t)gid * 32       + ck*8 + qid];
            ql[ck][1] = qlp[(size_t)(gid + 8) * 32 + ck*8 + qid];
            ql[ck][2] = qlp[(size_t)gid * 32       + ck*8 + qid + 4];
            ql[ck][3] = qlp[(size_t)(gid + 8) * 32 + ck*8 + qid + 4];
        }
    }

    #define ATTN_ISSUE(BUFSEL, KT) do {                                              \
        _Pragma("unroll")                                                            \
        for (int j = 0; j < 4; j++) {                                                \
            int idx = tid + j * 128;                                                 \
            int r = idx >> 3, c4 = (idx & 7) * 4;                                    \
            cp_async16(smbase + ((SMAOFF(BUFSEL,0) + r*36 + c4) << 2),               \
                       kHb + (size_t)((KT)*64 + r) * 32 + c4);                       \
            cp_async16(smbase + ((SMAOFF(BUFSEL,1) + r*36 + c4) << 2),               \
                       kLb + (size_t)((KT)*64 + r) * 32 + c4);                       \
            cp_async16(smbase + ((SMAOFF(BUFSEL,2) + r*36 + c4) << 2),               \
                       vHb + (size_t)r * 1024 + (KT)*32 + c4);                       \
            cp_async16(smbase + ((SMAOFF(BUFSEL,3) + r*36 + c4) << 2),               \
                       vLb + (size_t)r * 1024 + (KT)*32 + c4);                       \
        }                                                                            \
    } while (0)

    float m1 = -INFINITY, m2 = -INFINITY, l1 = 0.f, l2 = 0.f;
    float o[8][4];
    #pragma unroll
    for (int t = 0; t < 8; t++)
        #pragma unroll
        for (int j = 0; j < 4; j++) o[t][j] = 0.f;

    ATTN_ISSUE(0, 0);
    cp_commit();

    int buf = 0;
    for (int kt = 0; kt < SEQ / 64; kt++) {
        // bias for this tile first (overlaps cp.async wait)
        float s[8][4];
        #pragma unroll
        for (int tn = 0; tn < 8; tn++) {
            float2 b01 = *(const float2*)(bb + (size_t)gid * SEQ       + kt*64 + tn*8 + qid*2);
            float2 b23 = *(const float2*)(bb + (size_t)(gid + 8) * SEQ + kt*64 + tn*8 + qid*2);
            s[tn][0] = b01.x; s[tn][1] = b01.y; s[tn][2] = b23.x; s[tn][3] = b23.y;
        }

        cp_wait0();
        __syncthreads();
        if (kt + 1 < SEQ / 64) { ATTN_ISSUE(buf ^ 1, kt + 1); cp_commit(); }

        // S += Q K^T (3-term)
        #pragma unroll
        for (int ck = 0; ck < 4; ck++) {
            #pragma unroll
            for (int tnp = 0; tnp < 4; tnp++) {
                unsigned kh[4], kl[4];
                unsigned rowoff = (tnp * 16 + b_r) * 36 + ck * 8 + b_c;
                ldsm_x4(kh[0], kh[1], kh[2], kh[3], smbase + ((SMAOFF(buf,0) + rowoff) << 2));
                ldsm_x4(kl[0], kl[1], kl[2], kl[3], smbase + ((SMAOFF(buf,1) + rowoff) << 2));
                #pragma unroll
                for (int e = 0; e < 2; e++) {
                    int tn = tnp * 2 + e;
                    mma_bf16(s[tn], qh[ck][0], qh[ck][1], qh[ck][2], qh[ck][3], kh[e*2], kh[e*2+1]);
                    mma_bf16(s[tn], qh[ck][0], qh[ck][1], qh[ck][2], qh[ck][3], kl[e*2], kl[e*2+1]);
                    mma_bf16(s[tn], ql[ck][0], ql[ck][1], ql[ck][2], ql[ck][3], kh[e*2], kh[e*2+1]);
                }
            }
        }

        // online softmax
        float rmax1 = -INFINITY, rmax2 = -INFINITY;
        #pragma unroll
        for (int tn = 0; tn < 8; tn++) {
            rmax1 = fmaxf(rmax1, fmaxf(s[tn][0], s[tn][1]));
            rmax2 = fmaxf(rmax2, fmaxf(s[tn][2], s[tn][3]));
        }
        rmax1 = fmaxf(rmax1, __shfl_xor_sync(0xffffffffu, rmax1, 1));
        rmax1 = fmaxf(rmax1, __shfl_xor_sync(0xffffffffu, rmax1, 2));
        rmax2 = fmaxf(rmax2, __shfl_xor_sync(0xffffffffu, rmax2, 1));
        rmax2 = fmaxf(rmax2, __shfl_xor_sync(0xffffffffu, rmax2, 2));

        float mn1 = fmaxf(m1, rmax1), mn2 = fmaxf(m2, rmax2);
        float sc1 = __expf(m1 - mn1), sc2 = __expf(m2 - mn2);
        m1 = mn1; m2 = mn2;

        float sum1 = 0.f, sum2 = 0.f;
        #pragma unroll
        for (int tn = 0; tn < 8; tn++) {
            s[tn][0] = __expf(s[tn][0] - mn1); sum1 += s[tn][0];
            s[tn][1] = __expf(s[tn][1] - mn1); sum1 += s[tn][1];
            s[tn][2] = __expf(s[tn][2] - mn2); sum2 += s[tn][2];
            s[tn][3] = __expf(s[tn][3] - mn2); sum2 += s[tn][3];
        }
        sum1 += __shfl_xor_sync(0xffffffffu, sum1, 1);
        sum1 += __shfl_xor_sync(0xffffffffu, sum1, 2);
        sum2 += __shfl_xor_sync(0xffffffffu, sum2, 1);
        sum2 += __shfl_xor_sync(0xffffffffu, sum2, 2);
        l1 = l1 * sc1 + sum1;
        l2 = l2 * sc2 + sum2;

        #pragma unroll
        for (int tn = 0; tn < 8; tn++) {
            o[tn][0] *= sc1; o[tn][1] *= sc1; o[tn][2] *= sc2; o[tn][3] *= sc2;
        }

        // O += P @ V (3-term: ph*vh + ph*vl + pl*vh)
        #pragma unroll
        for (int ck = 0; ck < 4; ck++) {
            unsigned ph[4], pl[4];
            split2(s[2*ck  ][0], s[2*ck  ][1], ph[0], pl[0]);
            split2(s[2*ck  ][2], s[2*ck  ][3], ph[1], pl[1]);
            split2(s[2*ck+1][0], s[2*ck+1][1], ph[2], pl[2]);
            split2(s[2*ck+1][2], s[2*ck+1][3], ph[3], pl[3]);
            #pragma unroll
            for (int tnp = 0; tnp < 4; tnp++) {
                unsigned vh[4], vl[4];
                unsigned rowoff = (tnp * 16 + b_r) * 36 + ck * 8 + b_c;
                ldsm_x4(vh[0], vh[1], vh[2], vh[3], smbase + ((SMAOFF(buf,2) + rowoff) << 2));
                ldsm_x4(vl[0], vl[1], vl[2], vl[3], smbase + ((SMAOFF(buf,3) + rowoff) << 2));
                #pragma unroll
                for (int e = 0; e < 2; e++) {
                    int tn = tnp * 2 + e;
                    mma_bf16(o[tn], ph[0], ph[1], ph[2], ph[3], vh[e*2], vh[e*2+1]);
                    mma_bf16(o[tn], ph[0], ph[1], ph[2], ph[3], vl[e*2], vl[e*2+1]);
                    mma_bf16(o[tn], pl[0], pl[1], pl[2], pl[3], vh[e*2], vh[e*2+1]);
                }
            }
        }
        buf ^= 1;
    }

    // epilogue: normalize, split, write CTX rows (8192 + b*2048 + s)
    float inv1 = 1.f / l1, inv2 = 1.f / l2;
    int s1 = q0 + warp * 16 + gid;
    int s2 = s1 + 8;
    size_t row1 = (size_t)(8192 + b * 2048 + s1) * 512;
    size_t row2 = (size_t)(8192 + b * 2048 + s2) * 512;
    #pragma unroll
    for (int tn = 0; tn < 8; tn++) {
        int pair = h * 32 + tn * 4 + qid;
        unsigned hi, lo;
        split2(o[tn][0] * inv1, o[tn][1] * inv1, hi, lo);
        g_ah[row1 + pair] = hi; g_al[row1 + pair] = lo;
        split2(o[tn][2] * inv2, o[tn][3] * inv2, hi, lo);
        g_ah[row2 + pair] = hi; g_al[row2 + pair] = lo;
    }
}

// ---------------------------------------------------------------------------
extern "C" void kernel_launch(void* const* d_in, const int* in_sizes, int n_in,
                              void* d_out, int out_size)
{
    const float* x    = (const float*)d_in[0];
    const float* bias = (const float*)d_in[1];
    const float* wq   = (const float*)d_in[2];
    const float* wk   = (const float*)d_in[3];
    const float* wv   = (const float*)d_in[4];
    const float* wo   = (const float*)d_in[5];
    float* out = (float*)d_out;

    cudaFuncSetAttribute(gemm_kernel, cudaFuncAttributeMaxDynamicSharedMemorySize, 81920);
    cudaFuncSetAttribute(attn_kernel, cudaFuncAttributeMaxDynamicSharedMemorySize, 73728);

    split_kernel<<<16384, 256>>>(x, wq, wk, wv, wo);
    gemm_kernel<<<dim3(8, 32, 3), 256, 81920>>>(0, nullptr);
    attn_kernel<<<dim3(2, 512), 128, 73728>>>(bias);
    gemm_kernel<<<dim3(8, 32, 1), 256, 81920>>>(3, out);
}